// round 3
// baseline (speedup 1.0000x reference)
#include <cuda_runtime.h>

// Router: logits = x @ wg^T + gr @ gm^T ; std-normalized softmax; top-2;
// mask expert E-1; renormalize.
// Output layout (float32): [gates 2T | indices 2T | logits 8T]
//
// R3: smem wg (R2 showed L1-__ldg wg floods the L1tex wavefront queue:
// 40 wf/warp-iter vs 8). NT=2 + launch_bounds(256,3) -> 24 warps/SM
// (R1 was reg-bound at 16 warps/SM, issue=23%, latency-exposed).

constexpr int D       = 2048;
constexpr int E       = 8;
constexpr int NT      = 2;            // tokens per warp (register-blocked)
constexpr int THREADS = 256;
constexpr int WARPS   = THREADS / 32;
constexpr int CHUNKS  = D / 4;        // 16B chunks per row = 512
constexpr int ITERS   = CHUNKS / 32;  // 16 per-lane iterations
constexpr int SMEM_BYTES = (E * D + 64) * 4;   // wg + gm = 65792 B
constexpr int GRID    = 512;          // 4096 warps, exactly 2 groups each

__device__ __forceinline__ unsigned long long ffma2(unsigned long long a,
                                                    unsigned long long b,
                                                    unsigned long long c) {
    unsigned long long d;
    asm("fma.rn.f32x2 %0, %1, %2, %3;" : "=l"(d) : "l"(a), "l"(b), "l"(c));
    return d;
}

__device__ __forceinline__ float pairsum(unsigned long long v) {
    float2 f;
    f.x = __uint_as_float((unsigned int)(v & 0xffffffffull));
    f.y = __uint_as_float((unsigned int)(v >> 32));
    return f.x + f.y;
}

__global__ void __launch_bounds__(THREADS, 3)
router_kernel(const float* __restrict__ x,
              const float* __restrict__ wg,
              const float* __restrict__ gm,
              const float* __restrict__ gr,
              float* __restrict__ out_gates,
              float* __restrict__ out_idx,
              float* __restrict__ out_logits,
              int nGroups) {
    extern __shared__ float smem[];
    float4* s_wg4 = reinterpret_cast<float4*>(smem);            // [E][D] floats
    float*  s_gm  = smem + E * D;                               // [E][E]

    // Stage wg + gm into shared once per CTA (L2-served after 1st CTA).
    const float4* wg4 = reinterpret_cast<const float4*>(wg);
    for (int i = threadIdx.x; i < E * CHUNKS; i += THREADS) s_wg4[i] = wg4[i];
    if (threadIdx.x < E * E) s_gm[threadIdx.x] = gm[threadIdx.x];
    __syncthreads();

    const ulonglong2* s_w2 = reinterpret_cast<const ulonglong2*>(smem);

    const int lane     = threadIdx.x & 31;
    const int gwarp    = blockIdx.x * WARPS + (threadIdx.x >> 5);
    const int totWarps = gridDim.x * WARPS;

    for (int g = gwarp; g < nGroups; g += totWarps) {
        const int t0 = g * NT;

        unsigned long long acc[NT][E];
        #pragma unroll
        for (int j = 0; j < NT; j++)
            #pragma unroll
            for (int e = 0; e < E; e++) acc[j][e] = 0ull;

        const float4* xr0 = reinterpret_cast<const float4*>(x + (size_t)t0 * D);
        const float4* xr1 = reinterpret_cast<const float4*>(x + (size_t)(t0 + 1) * D);

        #pragma unroll 4
        for (int it = 0; it < ITERS; it++) {
            const int c = it * 32 + lane;           // 16B-chunk index in row
            // streaming: keep x out of the way of everything in L1/L2
            float4 xa = __ldcs(xr0 + c);
            float4 xb = __ldcs(xr1 + c);
            unsigned long long x0lo =
                ((unsigned long long)__float_as_uint(xa.y) << 32) | __float_as_uint(xa.x);
            unsigned long long x0hi =
                ((unsigned long long)__float_as_uint(xa.w) << 32) | __float_as_uint(xa.z);
            unsigned long long x1lo =
                ((unsigned long long)__float_as_uint(xb.y) << 32) | __float_as_uint(xb.x);
            unsigned long long x1hi =
                ((unsigned long long)__float_as_uint(xb.w) << 32) | __float_as_uint(xb.z);
            #pragma unroll
            for (int e = 0; e < E; e++) {
                ulonglong2 wv = s_w2[e * CHUNKS + c];
                acc[0][e] = ffma2(x0lo, wv.x, acc[0][e]);
                acc[0][e] = ffma2(x0hi, wv.y, acc[0][e]);
                acc[1][e] = ffma2(x1lo, wv.x, acc[1][e]);
                acc[1][e] = ffma2(x1hi, wv.y, acc[1][e]);
            }
        }

        // Butterfly reduction: every lane ends with the full dot products.
        float red[NT][E];
        #pragma unroll
        for (int j = 0; j < NT; j++) {
            #pragma unroll
            for (int e = 0; e < E; e++) {
                float s = pairsum(acc[j][e]);
                #pragma unroll
                for (int off = 16; off > 0; off >>= 1)
                    s += __shfl_xor_sync(0xffffffffu, s, off);
                red[j][e] = s;
            }
        }

        // Lane j (< NT) owns token t0+j.
        float logit[E];
        #pragma unroll
        for (int e = 0; e < E; e++) {
            float v = red[0][e];
            if (lane == 1) v = red[1][e];
            logit[e] = v;
        }

        if (lane < NT) {
            const int t = t0 + lane;

            // gate_map residual: logit[f] += sum_e gr[t][e] * gm[f][e]
            float4 g0 = __ldg(reinterpret_cast<const float4*>(gr + (size_t)t * E));
            float4 g1 = __ldg(reinterpret_cast<const float4*>(gr + (size_t)t * E + 4));
            float grv[8] = {g0.x, g0.y, g0.z, g0.w, g1.x, g1.y, g1.z, g1.w};
            float lg[E];
            #pragma unroll
            for (int f = 0; f < E; f++) {
                float s = logit[f];
                #pragma unroll
                for (int e = 0; e < E; e++) s = fmaf(grv[e], s_gm[f * E + e], s);
                lg[f] = s;
            }

            // unbiased std (ddof=1) over E=8
            float mean = 0.f;
            #pragma unroll
            for (int f = 0; f < E; f++) mean += lg[f];
            mean *= (1.f / E);
            float var = 0.f;
            #pragma unroll
            for (int f = 0; f < E; f++) {
                float d = lg[f] - mean;
                var = fmaf(d, d, var);
            }
            float inv_std = rsqrtf(var * (1.f / (E - 1)));

            // softmax(lg * inv_std)
            float z[E], m = -3.402823466e+38f;
            #pragma unroll
            for (int f = 0; f < E; f++) {
                z[f] = lg[f] * inv_std;
                m = fmaxf(m, z[f]);
            }
            float p[E], psum = 0.f;
            #pragma unroll
            for (int f = 0; f < E; f++) {
                p[f] = __expf(z[f] - m);
                psum += p[f];
            }
            float inv_psum = 1.f / psum;
            #pragma unroll
            for (int f = 0; f < E; f++) p[f] *= inv_psum;

            // stable top-2 (descending, lower index wins ties)
            int i1 = 0; float v1 = p[0];
            #pragma unroll
            for (int f = 1; f < E; f++)
                if (p[f] > v1) { v1 = p[f]; i1 = f; }
            int i2; float v2;
            if (i1 == 0) { i2 = 1; v2 = p[1]; } else { i2 = 0; v2 = p[0]; }
            #pragma unroll
            for (int f = 1; f < E; f++)
                if (f != i1 && p[f] > v2) { v2 = p[f]; i2 = f; }

            // mask last expert, renormalize over the 2 selected
            float gg1 = (i1 == E - 1) ? 0.f : v1;
            float gg2 = (i2 == E - 1) ? 0.f : v2;
            float inv_s = 1.f / (gg1 + gg2);
            gg1 *= inv_s; gg2 *= inv_s;

            float2 gpair; gpair.x = gg1; gpair.y = gg2;
            *reinterpret_cast<float2*>(out_gates + (size_t)2 * t) = gpair;
            float2 ipair; ipair.x = (float)i1; ipair.y = (float)i2;
            *reinterpret_cast<float2*>(out_idx + (size_t)2 * t) = ipair;

            float4 L0; L0.x = lg[0]; L0.y = lg[1]; L0.z = lg[2]; L0.w = lg[3];
            float4 L1; L1.x = lg[4]; L1.y = lg[5]; L1.z = lg[6]; L1.w = lg[7];
            float4* olr = reinterpret_cast<float4*>(out_logits + (size_t)t * E);
            olr[0] = L0;
            olr[1] = L1;
        }
    }
}

extern "C" void kernel_launch(void* const* d_in, const int* in_sizes, int n_in,
                              void* d_out, int out_size) {
    const float* x  = (const float*)d_in[0];   // [T, D]
    const float* wg = (const float*)d_in[1];   // [E, D]
    const float* gm = (const float*)d_in[2];   // [E, E]
    const float* gr = (const float*)d_in[3];   // [T, E]

    const int T = in_sizes[0] / D;
    float* out       = (float*)d_out;
    float* out_gates = out;                       // [T,2]
    float* out_idx   = out + (size_t)2 * T;       // [T,2] as float
    float* out_logit = out + (size_t)4 * T;       // [T,8]

    cudaFuncSetAttribute(router_kernel,
                         cudaFuncAttributeMaxDynamicSharedMemorySize,
                         SMEM_BYTES);

    const int nGroups = T / NT;
    router_kernel<<<GRID, THREADS, SMEM_BYTES>>>(x, wg, gm, gr,
                                                 out_gates, out_idx, out_logit,
                                                 nGroups);
}

// round 4
// speedup vs baseline: 1.2078x; 1.2078x over previous
#include <cuda_runtime.h>

// Router: logits = x @ wg^T + gr @ gm^T ; std-normalized softmax; top-2;
// mask expert E-1; renormalize.
// Output layout (float32): [gates 2T | indices 2T | logits 8T]
//
// R4: latency-bound diagnosis (R1-R3: all pipes <45%). Fix: per-warp
// cp.async (LDGSTS) triple-buffered x staging -> in-flight load bytes
// decoupled from registers. NT=4 wg-reuse kept; wg stays in smem.

constexpr int D       = 2048;
constexpr int E       = 8;
constexpr int NT      = 4;            // tokens per warp
constexpr int THREADS = 256;
constexpr int WARPS   = THREADS / 32;
constexpr int CHUNKS  = D / 4;        // 16B chunks per row = 512
constexpr int ITERS   = CHUNKS / 32;  // 16 per-lane iterations
constexpr int DEPTH   = 3;            // cp.async pipeline stages
constexpr int GRID    = 256;          // 2048 warps x 2 groups each

// smem floats: wg [E*D] | gm [64] | x-ring [WARPS*DEPTH*NT*128]
constexpr int XOFF_FLOATS = E * D + 64;                       // 16448
constexpr int X_FLOATS    = WARPS * DEPTH * NT * 128;         // 12288
constexpr int SMEM_BYTES  = (XOFF_FLOATS + X_FLOATS) * 4;     // 114944 B

__device__ __forceinline__ unsigned long long ffma2(unsigned long long a,
                                                    unsigned long long b,
                                                    unsigned long long c) {
    unsigned long long d;
    asm("fma.rn.f32x2 %0, %1, %2, %3;" : "=l"(d) : "l"(a), "l"(b), "l"(c));
    return d;
}

__device__ __forceinline__ float pairsum(unsigned long long v) {
    float2 f;
    f.x = __uint_as_float((unsigned int)(v & 0xffffffffull));
    f.y = __uint_as_float((unsigned int)(v >> 32));
    return f.x + f.y;
}

__device__ __forceinline__ void cp16(unsigned int dst_smem, const void* src) {
    asm volatile("cp.async.cg.shared.global [%0], [%1], 16;\n"
                 :: "r"(dst_smem), "l"(src) : "memory");
}

__device__ __forceinline__ void pack4(float4 v, unsigned long long& lo,
                                      unsigned long long& hi) {
    lo = ((unsigned long long)__float_as_uint(v.y) << 32) | __float_as_uint(v.x);
    hi = ((unsigned long long)__float_as_uint(v.w) << 32) | __float_as_uint(v.z);
}

__global__ void __launch_bounds__(THREADS, 2)
router_kernel(const float* __restrict__ x,
              const float* __restrict__ wg,
              const float* __restrict__ gm,
              const float* __restrict__ gr,
              float* __restrict__ out_gates,
              float* __restrict__ out_idx,
              float* __restrict__ out_logits,
              int nGroups) {
    extern __shared__ float smem[];
    float4* s_wg4 = reinterpret_cast<float4*>(smem);            // [E][D]
    float*  s_gm  = smem + E * D;                               // [E][E]

    const float4* wg4 = reinterpret_cast<const float4*>(wg);
    for (int i = threadIdx.x; i < E * CHUNKS; i += THREADS) s_wg4[i] = wg4[i];
    if (threadIdx.x < E * E) s_gm[threadIdx.x] = gm[threadIdx.x];
    __syncthreads();

    const ulonglong2* s_w2 = reinterpret_cast<const ulonglong2*>(smem);

    const int lane  = threadIdx.x & 31;
    const int wid   = threadIdx.x >> 5;
    const int gwarp = blockIdx.x * WARPS + wid;
    const int totWarps = gridDim.x * WARPS;

    // This warp's private x staging ring: DEPTH slots of NT*32 float4.
    float4* s_x4 = reinterpret_cast<float4*>(smem + XOFF_FLOATS)
                   + wid * (DEPTH * NT * 32);
    const unsigned int xs_addr =
        (unsigned int)__cvta_generic_to_shared(s_x4) + lane * 16;

    for (int g = gwarp; g < nGroups; g += totWarps) {
        const int t0 = g * NT;

        const float4* xr0 = reinterpret_cast<const float4*>(x + (size_t)t0 * D);
        const float4* xr1 = reinterpret_cast<const float4*>(x + (size_t)(t0 + 1) * D);
        const float4* xr2 = reinterpret_cast<const float4*>(x + (size_t)(t0 + 2) * D);
        const float4* xr3 = reinterpret_cast<const float4*>(x + (size_t)(t0 + 3) * D);

        unsigned long long acc[NT][E];
        #pragma unroll
        for (int j = 0; j < NT; j++)
            #pragma unroll
            for (int e = 0; e < E; e++) acc[j][e] = 0ull;

        // ---- pipeline prologue: issue stages 0..DEPTH-1 ----
        #pragma unroll
        for (int s = 0; s < DEPTH; s++) {
            const unsigned int dst = xs_addr + s * (NT * 512);
            const int c = s * 32 + lane;
            cp16(dst,            xr0 + c);
            cp16(dst + 512,      xr1 + c);
            cp16(dst + 1024,     xr2 + c);
            cp16(dst + 1536,     xr3 + c);
            asm volatile("cp.async.commit_group;\n" ::: "memory");
        }

        int cslot = 0;       // consume slot
        int islot = 0;       // issue slot (for stage it+DEPTH)
        #pragma unroll 4
        for (int it = 0; it < ITERS; it++) {
            // stage `it` complete when <= DEPTH-1 groups remain pending
            asm volatile("cp.async.wait_group %0;\n" :: "n"(DEPTH - 1) : "memory");

            const float4* xb = s_x4 + cslot * (NT * 32);
            float4 xa0 = xb[lane];
            float4 xa1 = xb[32 + lane];
            float4 xa2 = xb[64 + lane];
            float4 xa3 = xb[96 + lane];
            if (++cslot == DEPTH) cslot = 0;

            unsigned long long x0lo, x0hi, x1lo, x1hi, x2lo, x2hi, x3lo, x3hi;
            pack4(xa0, x0lo, x0hi);
            pack4(xa1, x1lo, x1hi);
            pack4(xa2, x2lo, x2hi);
            pack4(xa3, x3lo, x3hi);

            const int cw = it * 32 + lane;
            #pragma unroll
            for (int e = 0; e < E; e++) {
                ulonglong2 wv = s_w2[e * CHUNKS + cw];
                acc[0][e] = ffma2(x0lo, wv.x, acc[0][e]);
                acc[0][e] = ffma2(x0hi, wv.y, acc[0][e]);
                acc[1][e] = ffma2(x1lo, wv.x, acc[1][e]);
                acc[1][e] = ffma2(x1hi, wv.y, acc[1][e]);
                acc[2][e] = ffma2(x2lo, wv.x, acc[2][e]);
                acc[2][e] = ffma2(x2hi, wv.y, acc[2][e]);
                acc[3][e] = ffma2(x3lo, wv.x, acc[3][e]);
                acc[3][e] = ffma2(x3hi, wv.y, acc[3][e]);
            }

            // issue stage it+DEPTH (empty group on tail keeps counts uniform)
            const int s = it + DEPTH;
            if (s < ITERS) {
                const unsigned int dst = xs_addr + islot * (NT * 512);
                const int c = s * 32 + lane;
                cp16(dst,            xr0 + c);
                cp16(dst + 512,      xr1 + c);
                cp16(dst + 1024,     xr2 + c);
                cp16(dst + 1536,     xr3 + c);
            }
            asm volatile("cp.async.commit_group;\n" ::: "memory");
            if (++islot == DEPTH) islot = 0;
        }

        // Butterfly reduction: every lane ends with the full dot products.
        float red[NT][E];
        #pragma unroll
        for (int j = 0; j < NT; j++) {
            #pragma unroll
            for (int e = 0; e < E; e++) {
                float s = pairsum(acc[j][e]);
                #pragma unroll
                for (int off = 16; off > 0; off >>= 1)
                    s += __shfl_xor_sync(0xffffffffu, s, off);
                red[j][e] = s;
            }
        }

        float logit[E];
        #pragma unroll
        for (int e = 0; e < E; e++) {
            float v = red[0][e];
            if (lane == 1) v = red[1][e];
            if (lane == 2) v = red[2][e];
            if (lane == 3) v = red[3][e];
            logit[e] = v;
        }

        if (lane < NT) {
            const int t = t0 + lane;

            float4 g0 = __ldg(reinterpret_cast<const float4*>(gr + (size_t)t * E));
            float4 g1 = __ldg(reinterpret_cast<const float4*>(gr + (size_t)t * E + 4));
            float grv[8] = {g0.x, g0.y, g0.z, g0.w, g1.x, g1.y, g1.z, g1.w};
            float lg[E];
            #pragma unroll
            for (int f = 0; f < E; f++) {
                float s = logit[f];
                #pragma unroll
                for (int e = 0; e < E; e++) s = fmaf(grv[e], s_gm[f * E + e], s);
                lg[f] = s;
            }

            float mean = 0.f;
            #pragma unroll
            for (int f = 0; f < E; f++) mean += lg[f];
            mean *= (1.f / E);
            float var = 0.f;
            #pragma unroll
            for (int f = 0; f < E; f++) {
                float d = lg[f] - mean;
                var = fmaf(d, d, var);
            }
            float inv_std = rsqrtf(var * (1.f / (E - 1)));

            float z[E], m = -3.402823466e+38f;
            #pragma unroll
            for (int f = 0; f < E; f++) {
                z[f] = lg[f] * inv_std;
                m = fmaxf(m, z[f]);
            }
            float p[E], psum = 0.f;
            #pragma unroll
            for (int f = 0; f < E; f++) {
                p[f] = __expf(z[f] - m);
                psum += p[f];
            }
            float inv_psum = 1.f / psum;
            #pragma unroll
            for (int f = 0; f < E; f++) p[f] *= inv_psum;

            int i1 = 0; float v1 = p[0];
            #pragma unroll
            for (int f = 1; f < E; f++)
                if (p[f] > v1) { v1 = p[f]; i1 = f; }
            int i2; float v2;
            if (i1 == 0) { i2 = 1; v2 = p[1]; } else { i2 = 0; v2 = p[0]; }
            #pragma unroll
            for (int f = 1; f < E; f++)
                if (f != i1 && p[f] > v2) { v2 = p[f]; i2 = f; }

            float gg1 = (i1 == E - 1) ? 0.f : v1;
            float gg2 = (i2 == E - 1) ? 0.f : v2;
            float inv_s = 1.f / (gg1 + gg2);
            gg1 *= inv_s; gg2 *= inv_s;

            float2 gpair; gpair.x = gg1; gpair.y = gg2;
            *reinterpret_cast<float2*>(out_gates + (size_t)2 * t) = gpair;
            float2 ipair; ipair.x = (float)i1; ipair.y = (float)i2;
            *reinterpret_cast<float2*>(out_idx + (size_t)2 * t) = ipair;

            float4 L0; L0.x = lg[0]; L0.y = lg[1]; L0.z = lg[2]; L0.w = lg[3];
            float4 L1; L1.x = lg[4]; L1.y = lg[5]; L1.z = lg[6]; L1.w = lg[7];
            float4* olr = reinterpret_cast<float4*>(out_logits + (size_t)t * E);
            olr[0] = L0;
            olr[1] = L1;
        }
    }

    // drain any still-pending async copies before exit
    asm volatile("cp.async.wait_group 0;\n" ::: "memory");
}

extern "C" void kernel_launch(void* const* d_in, const int* in_sizes, int n_in,
                              void* d_out, int out_size) {
    const float* x  = (const float*)d_in[0];   // [T, D]
    const float* wg = (const float*)d_in[1];   // [E, D]
    const float* gm = (const float*)d_in[2];   // [E, E]
    const float* gr = (const float*)d_in[3];   // [T, E]

    const int T = in_sizes[0] / D;
    float* out       = (float*)d_out;
    float* out_gates = out;                       // [T,2]
    float* out_idx   = out + (size_t)2 * T;       // [T,2] as float
    float* out_logit = out + (size_t)4 * T;       // [T,8]

    cudaFuncSetAttribute(router_kernel,
                         cudaFuncAttributeMaxDynamicSharedMemorySize,
                         SMEM_BYTES);

    const int nGroups = T / NT;
    router_kernel<<<GRID, THREADS, SMEM_BYTES>>>(x, wg, gm, gr,
                                                 out_gates, out_idx, out_logit,
                                                 nGroups);
}